// round 5
// baseline (speedup 1.0000x reference)
#include <cuda_runtime.h>

#define NN 100000
#define EE 1200000
#define GG 128
#define HID 64

// ---------------- scratch (static device globals only) ----------------
__device__ int   g_deg[NN];
__device__ int   g_rowptr[NN + 1];
__device__ int   g_cursor[NN];
__device__ int   g_csr_src[EE];
__device__ float g_buf[2][(size_t)NN * HID];   // 0: z scratch, 1: h
__device__ float g_s[NN];                      // per-node dot(h, w_out)

// ---------------- CSR build ----------------
__global__ void zero_deg_kernel() {
    int i = blockIdx.x * blockDim.x + threadIdx.x;
    if (i < NN) g_deg[i] = 0;
}

__global__ void hist_kernel(const int* __restrict__ dst) {
    int e = blockIdx.x * blockDim.x + threadIdx.x;
    if (e < EE) atomicAdd(&g_deg[dst[e]], 1);
}

// single-block exclusive scan of g_deg -> g_rowptr (and cursor copy)
__global__ void scan_kernel() {
    const int T = 1024;
    int t = threadIdx.x;
    const int CH = (NN + T - 1) / T;       // 98
    int start = t * CH;
    int end = start + CH; if (end > NN) end = NN;
    if (start > NN) start = NN;

    int sum = 0;
    for (int i = start; i < end; i++) sum += g_deg[i];

    __shared__ int wtot[32];
    int lane = t & 31, w = t >> 5;
    int v = sum;
#pragma unroll
    for (int off = 1; off < 32; off <<= 1) {
        int u = __shfl_up_sync(0xffffffffu, v, off);
        if (lane >= off) v += u;
    }
    if (lane == 31) wtot[w] = v;
    __syncthreads();
    if (w == 0) {
        int wv = wtot[lane];
#pragma unroll
        for (int off = 1; off < 32; off <<= 1) {
            int u = __shfl_up_sync(0xffffffffu, wv, off);
            if (lane >= off) wv += u;
        }
        wtot[lane] = wv;
    }
    __syncthreads();
    int ex = v - sum + (w ? wtot[w - 1] : 0);   // exclusive prefix for this thread's chunk
    int run = ex;
    for (int i = start; i < end; i++) {
        g_rowptr[i] = run;
        g_cursor[i] = run;
        run += g_deg[i];
    }
    if (t == T - 1) g_rowptr[NN] = run;         // == EE
}

__global__ void scatter_kernel(const int* __restrict__ src, const int* __restrict__ dst) {
    int e = blockIdx.x * blockDim.x + threadIdx.x;
    if (e < EE) {
        int d = dst[e];
        int p = atomicAdd(&g_cursor[d], 1);
        g_csr_src[p] = src[e];
    }
}

// ---------------- aggregation (pull via CSR, warp per node) ----------------
// layer 0: x is [N,30]; write z padded to stride 32 into g_buf[0]
__global__ void agg30_kernel(const float* __restrict__ x, const float* __restrict__ eps_p) {
    int node = (blockIdx.x * blockDim.x + threadIdx.x) >> 5;
    if (node >= NN) return;
    int lane = threadIdx.x & 31;
    int beg = g_rowptr[node], end = g_rowptr[node + 1];
    float acc = 0.f;
    if (lane < 30) {
        for (int j = beg; j < end; j++) {
            int s = g_csr_src[j];
            acc += x[(size_t)s * 30 + lane];
        }
        acc += (1.0f + *eps_p) * x[(size_t)node * 30 + lane];
    }
    g_buf[0][(size_t)node * 32 + lane] = (lane < 30) ? acc : 0.f;
}

// layers 1..3: h = g_buf[1] [N,64]; write z [N,64] to g_buf[0]
__global__ void agg64_kernel(const float* __restrict__ eps_p) {
    int node = (blockIdx.x * blockDim.x + threadIdx.x) >> 5;
    if (node >= NN) return;
    int lane = threadIdx.x & 31;
    const float* __restrict__ h = g_buf[1];
    float* __restrict__ z = g_buf[0];
    int beg = g_rowptr[node], end = g_rowptr[node + 1];
    float ax = 0.f, ay = 0.f;
    for (int j = beg; j < end; j++) {
        int s = g_csr_src[j];
        float2 v = *(const float2*)(h + (size_t)s * 64 + lane * 2);
        ax += v.x; ay += v.y;
    }
    float e1 = 1.0f + *eps_p;
    float2 hv = *(const float2*)(h + (size_t)node * 64 + lane * 2);
    ax += e1 * hv.x; ay += e1 * hv.y;
    float2 o; o.x = ax; o.y = ay;
    *(float2*)(z + (size_t)node * 64 + lane * 2) = o;
}

// ---------------- fused 2-layer MLP: h = relu(z@w1+b1)@w2+b2 ----------------
// 64 nodes per block, 256 threads, 4x4 register tiles, smem-resident weights.
// DOT=true: additionally write g_s[node] = dot(h_row, w_out) (final layer).
template <int KIN, bool DOT>   // padded K of z (32 for layer0, 64 otherwise)
__global__ void __launch_bounds__(256) mlp_kernel(
    const float* __restrict__ w1, const float* __restrict__ b1,
    const float* __restrict__ w2, const float* __restrict__ b2,
    const float* __restrict__ wout,
    int kreal)
{
    __shared__ __align__(16) float zt[64 * 64];   // z tile, reused as hidden tile
    __shared__ __align__(16) float ws[64 * 64];   // w1 then w2
    __shared__ float wo[64];
    __shared__ float dred[64 * 17];               // per-node partial dots (padded: bank-conflict-free)

    const float* __restrict__ z = g_buf[0];
    float* __restrict__ hout = g_buf[1];

    int t = threadIdx.x;
    int n0g = blockIdx.x * 64;

    // load z tile (coalesced; stride KIN in global)
    for (int idx = t; idx < 64 * KIN; idx += 256) {
        int n = idx / KIN;
        int k = idx - n * KIN;
        int gn = n0g + n;
        zt[idx] = (gn < NN) ? z[(size_t)gn * KIN + k] : 0.f;
    }
    // load w1 (pad rows >= kreal with 0)
    for (int idx = t; idx < KIN * 64; idx += 256) {
        ws[idx] = (idx < kreal * 64) ? w1[idx] : 0.f;
    }
    if (DOT && t < 64) wo[t] = wout[t];
    __syncthreads();

    int tx = t & 15, ty = t >> 4;
    int o0 = tx * 4, n0 = ty * 4;

    float ac[4][4];
    {
        float4 bv = *(const float4*)(b1 + o0);
#pragma unroll
        for (int i = 0; i < 4; i++) {
            ac[i][0] = bv.x; ac[i][1] = bv.y; ac[i][2] = bv.z; ac[i][3] = bv.w;
        }
    }
    for (int k = 0; k < KIN; k += 4) {
        float za[4][4], wa[4][4];
#pragma unroll
        for (int i = 0; i < 4; i++) {
            float4 zv = *(const float4*)&zt[(n0 + i) * KIN + k];
            za[i][0] = zv.x; za[i][1] = zv.y; za[i][2] = zv.z; za[i][3] = zv.w;
        }
#pragma unroll
        for (int kk = 0; kk < 4; kk++) {
            float4 wv = *(const float4*)&ws[(k + kk) * 64 + o0];
            wa[kk][0] = wv.x; wa[kk][1] = wv.y; wa[kk][2] = wv.z; wa[kk][3] = wv.w;
        }
#pragma unroll
        for (int kk = 0; kk < 4; kk++)
#pragma unroll
            for (int i = 0; i < 4; i++)
#pragma unroll
                for (int oc = 0; oc < 4; oc++)
                    ac[i][oc] = fmaf(za[i][kk], wa[kk][oc], ac[i][oc]);
    }
    __syncthreads();

    // relu -> hidden tile (into zt, 64x64 layout); load w2
#pragma unroll
    for (int i = 0; i < 4; i++) {
        float4 hv;
        hv.x = fmaxf(ac[i][0], 0.f); hv.y = fmaxf(ac[i][1], 0.f);
        hv.z = fmaxf(ac[i][2], 0.f); hv.w = fmaxf(ac[i][3], 0.f);
        *(float4*)&zt[(n0 + i) * 64 + o0] = hv;
    }
    for (int idx = t; idx < 64 * 64; idx += 256) ws[idx] = w2[idx];
    __syncthreads();

    float ac2[4][4];
    {
        float4 bv = *(const float4*)(b2 + o0);
#pragma unroll
        for (int i = 0; i < 4; i++) {
            ac2[i][0] = bv.x; ac2[i][1] = bv.y; ac2[i][2] = bv.z; ac2[i][3] = bv.w;
        }
    }
    for (int k = 0; k < 64; k += 4) {
        float za[4][4], wa[4][4];
#pragma unroll
        for (int i = 0; i < 4; i++) {
            float4 zv = *(const float4*)&zt[(n0 + i) * 64 + k];
            za[i][0] = zv.x; za[i][1] = zv.y; za[i][2] = zv.z; za[i][3] = zv.w;
        }
#pragma unroll
        for (int kk = 0; kk < 4; kk++) {
            float4 wv = *(const float4*)&ws[(k + kk) * 64 + o0];
            wa[kk][0] = wv.x; wa[kk][1] = wv.y; wa[kk][2] = wv.z; wa[kk][3] = wv.w;
        }
#pragma unroll
        for (int kk = 0; kk < 4; kk++)
#pragma unroll
            for (int i = 0; i < 4; i++)
#pragma unroll
                for (int oc = 0; oc < 4; oc++)
                    ac2[i][oc] = fmaf(za[i][kk], wa[kk][oc], ac2[i][oc]);
    }

#pragma unroll
    for (int i = 0; i < 4; i++) {
        int gn = n0g + n0 + i;
        if (gn < NN) {
            float4 ov;
            ov.x = ac2[i][0]; ov.y = ac2[i][1]; ov.z = ac2[i][2]; ov.w = ac2[i][3];
            *(float4*)&hout[(size_t)gn * 64 + o0] = ov;
        }
    }

    if (DOT) {
        // partial dot over this thread's 4 output columns, per node row
#pragma unroll
        for (int i = 0; i < 4; i++) {
            float d = ac2[i][0] * wo[o0] + ac2[i][1] * wo[o0 + 1]
                    + ac2[i][2] * wo[o0 + 2] + ac2[i][3] * wo[o0 + 3];
            dred[(n0 + i) * 17 + tx] = d;
        }
        __syncthreads();
        // 64 nodes x 16 partials: reduce (deterministic order)
        if (t < 64) {
            float s = 0.f;
            const float* r = &dred[t * 17];
#pragma unroll
            for (int j = 0; j < 16; j++) s += r[j];
            int gn = n0g + t;
            if (gn < NN) g_s[gn] = s;
        }
    }
}

// batch is sorted -> binary search segment per graph; deterministic reduce.
__global__ void pool_kernel(const int* __restrict__ batch,
                            const float* __restrict__ b_out,
                            float* __restrict__ out) {
    int g = blockIdx.x;
    int lo = 0, hi = NN;
    while (lo < hi) { int m = (lo + hi) >> 1; if (batch[m] < g) lo = m + 1; else hi = m; }
    int s0 = lo;
    hi = NN;
    while (lo < hi) { int m = (lo + hi) >> 1; if (batch[m] <= g) lo = m + 1; else hi = m; }
    int s1 = lo;

    float sum = 0.f;
    for (int i = s0 + threadIdx.x; i < s1; i += blockDim.x) sum += g_s[i];
    __shared__ float red[256];
    red[threadIdx.x] = sum;
    __syncthreads();
    for (int st = 128; st; st >>= 1) {
        if (threadIdx.x < st) red[threadIdx.x] += red[threadIdx.x + st];
        __syncthreads();
    }
    if (threadIdx.x == 0) out[g] = red[0] + b_out[0];
}

// ---------------- launch ----------------
extern "C" void kernel_launch(void* const* d_in, const int* in_sizes, int n_in,
                              void* d_out, int out_size) {
    const float* x     = (const float*)d_in[0];
    const int*   ei    = (const int*)d_in[1];
    const int*   batch = (const int*)d_in[2];
    const float* eps0  = (const float*)d_in[3];
    const float* w1_0  = (const float*)d_in[4];
    const float* b1_0  = (const float*)d_in[5];
    const float* w2_0  = (const float*)d_in[6];
    const float* b2_0  = (const float*)d_in[7];
    const float* eps_r = (const float*)d_in[8];
    const float* w1_r  = (const float*)d_in[9];
    const float* b1_r  = (const float*)d_in[10];
    const float* w2_r  = (const float*)d_in[11];
    const float* b2_r  = (const float*)d_in[12];
    const float* w_out = (const float*)d_in[13];
    const float* b_out = (const float*)d_in[14];
    float* out = (float*)d_out;

    const int* src = ei;
    const int* dst = ei + EE;

    // CSR build
    zero_deg_kernel<<<(NN + 255) / 256, 256>>>();
    hist_kernel<<<(EE + 255) / 256, 256>>>(dst);
    scan_kernel<<<1, 1024>>>();
    scatter_kernel<<<(EE + 255) / 256, 256>>>(src, dst);

    int warp_blocks = (NN * 32 + 255) / 256;
    int mlp_blocks = (NN + 63) / 64;

    // layer 0: agg(x) -> z (g_buf[0]); MLP -> h (g_buf[1])
    agg30_kernel<<<warp_blocks, 256>>>(x, eps0);
    mlp_kernel<32, false><<<mlp_blocks, 256>>>(w1_0, b1_0, w2_0, b2_0, nullptr, 30);

    // layers 1..3: agg(h) -> z; MLP -> h (in place safe: agg fully reads h before MLP writes)
    for (int l = 0; l < 3; l++) {
        agg64_kernel<<<warp_blocks, 256>>>(eps_r + l);
        if (l < 2)
            mlp_kernel<64, false><<<mlp_blocks, 256>>>(
                w1_r + (size_t)l * 64 * 64, b1_r + (size_t)l * 64,
                w2_r + (size_t)l * 64 * 64, b2_r + (size_t)l * 64, nullptr, 64);
        else
            mlp_kernel<64, true><<<mlp_blocks, 256>>>(
                w1_r + (size_t)l * 64 * 64, b1_r + (size_t)l * 64,
                w2_r + (size_t)l * 64 * 64, b2_r + (size_t)l * 64, w_out, 64);
    }

    // pooled readout
    pool_kernel<<<GG, 256>>>(batch, b_out, out);
}